// round 1
// baseline (speedup 1.0000x reference)
#include <cuda_runtime.h>

// Fused Bayer demosaic:
//   y[n,c,i,j] = one of {center, plus-avg, diag-avg, h-avg, v-avg} of the
//   reflect-padded 3x3 neighborhood of x[n,0,i,j], chosen by (c, i&1, j&1).
//
// Quadrant -> (R,G,B) stencil map (decoded from the constant `sel` input):
//   q0 (i even, j even): (diag, plus, center)
//   q1 (i even, j odd ): (vavg, center, havg)
//   q2 (i odd , j even): (havg, center, vavg)
//   q3 (i odd , j odd ): (center, plus, diag)
//
// Pure HBM-streaming kernel: each thread produces 4 consecutive pixels
// (one float4 store per channel), reading 3 rows x 6 columns of input.

__device__ __forceinline__ void load_row6(const float* __restrict__ r,
                                          int j0, int W, bool fast,
                                          float v[6]) {
    if (fast) {
        float4 m = *reinterpret_cast<const float4*>(r + j0);
        v[0] = __ldg(r + j0 - 1);
        v[1] = m.x; v[2] = m.y; v[3] = m.z; v[4] = m.w;
        v[5] = __ldg(r + j0 + 4);
    } else {
#pragma unroll
        for (int k = 0; k < 6; ++k) {
            int c = j0 + k - 1;
            c = (c < 0) ? -c : c;                 // reflect: -1 -> 1
            c = (c >= W) ? (2 * W - 2 - c) : c;   // reflect: W -> W-2
            v[k] = __ldg(r + c);
        }
    }
}

__global__ __launch_bounds__(256) void bayer_demosaic_kernel(
    const float* __restrict__ x, float* __restrict__ y, int H, int W) {
    const int j0 = (blockIdx.x * blockDim.x + threadIdx.x) * 4;
    const int i  = blockIdx.y;
    const int n  = blockIdx.z;
    if (j0 >= W) return;

    const size_t plane = (size_t)H * W;
    const float* xp = x + (size_t)n * plane;

    const int im1 = (i == 0)     ? 1     : i - 1;   // reflect rows
    const int ip1 = (i == H - 1) ? H - 2 : i + 1;

    const float* ra = xp + (size_t)im1 * W;  // row above
    const float* rb = xp + (size_t)i   * W;  // center row
    const float* rc = xp + (size_t)ip1 * W;  // row below

    const bool fast = (j0 > 0) && (j0 + 4 < W);

    float a[6], b[6], c[6];
    load_row6(ra, j0, W, fast, a);
    load_row6(rb, j0, W, fast, b);
    load_row6(rc, j0, W, fast, c);

    float R[4], G[4], B[4];
    const int ip = i & 1;
#pragma unroll
    for (int t = 0; t < 4; ++t) {
        const float center = b[t + 1];
        const float plus   = 0.25f * ((a[t + 1] + c[t + 1]) + (b[t] + b[t + 2]));
        const float diag   = 0.25f * ((a[t] + a[t + 2]) + (c[t] + c[t + 2]));
        const float havg   = 0.5f  * (b[t] + b[t + 2]);
        const float vavg   = 0.5f  * (a[t + 1] + c[t + 1]);
        const int jp = t & 1;  // j0 is a multiple of 4, so parity of j == parity of t
        if (ip == 0) {
            if (jp == 0) { R[t] = diag;   G[t] = plus;   B[t] = center; }  // q0
            else         { R[t] = vavg;   G[t] = center; B[t] = havg;   }  // q1
        } else {
            if (jp == 0) { R[t] = havg;   G[t] = center; B[t] = vavg;   }  // q2
            else         { R[t] = center; G[t] = plus;   B[t] = diag;   }  // q3
        }
    }

    float* yn = y + (size_t)n * 3 * plane + (size_t)i * W + j0;
    *reinterpret_cast<float4*>(yn)             = make_float4(R[0], R[1], R[2], R[3]);
    *reinterpret_cast<float4*>(yn + plane)     = make_float4(G[0], G[1], G[2], G[3]);
    *reinterpret_cast<float4*>(yn + 2 * plane) = make_float4(B[0], B[1], B[2], B[3]);
}

extern "C" void kernel_launch(void* const* d_in, const int* in_sizes, int n_in,
                              void* d_out, int out_size) {
    const float* x = (const float*)d_in[0];
    float* y = (float*)d_out;

    const int H = 4096, W = 4096;
    const int N = in_sizes[0] / (H * W);  // = 2

    dim3 block(256, 1, 1);
    dim3 grid((W / 4 + 255) / 256, H, N);
    bayer_demosaic_kernel<<<grid, block>>>(x, y, H, W);
}